// round 13
// baseline (speedup 1.0000x reference)
#include <cuda_runtime.h>
#include <math.h>

// Problem constants
#define BATCH 256
#define SEQLEN 512
#define OBS 64
#define NNEUR 1024
#define ACT 64
#define KTOT (NNEUR + OBS)
#define NBLK 256             // persistent CTAs: 2/SM on 148 SMs, all co-resident

#define BETA_C 0.9f
#define VTH_C 1.0f

// ---------------- device scratch (static; no allocations) ----------------
__device__ float g_Wstk[KTOT * NNEUR];    // rows 0..1023: W_rec.T ; rows 1024..1087: W_in.T
__device__ float g_WoutT[NNEUR * ACT];    // (k, a)
__device__ float g_vA[BATCH * NNEUR];
__device__ float g_vB[BATCH * NNEUR];
__device__ float g_sA[BATCH * NNEUR];
__device__ float g_sB[BATCH * NNEUR];
__device__ unsigned g_count = 0;
__device__ unsigned g_sense = 0;          // monotonic phase; replay-safe

// ---------------- packed f32x2 helpers (Blackwell FFMA2) ----------------
// Each half is an independently rounded IEEE fp32 op == __fmaf_rn/__fadd_rn
// per element. Used ONLY inside the GEMM chains; per-element accumulation
// order is unchanged vs the scalar version.
__device__ __forceinline__ void fma2(unsigned long long& acc,
                                     unsigned long long a,
                                     unsigned long long b) {
    asm("fma.rn.f32x2 %0, %1, %2, %3;" : "=l"(acc) : "l"(a), "l"(b), "l"(acc));
}
__device__ __forceinline__ unsigned long long add2(unsigned long long a,
                                                   unsigned long long b) {
    unsigned long long d;
    asm("add.rn.f32x2 %0, %1, %2;" : "=l"(d) : "l"(a), "l"(b));
    return d;
}
union F2U { unsigned long long u; float2 f; };

// ---------------- software grid barrier (NBLK co-resident CTAs) ----------------
__device__ __forceinline__ void grid_barrier() {
    __syncthreads();
    if (threadIdx.x == 0) {
        unsigned s = *(volatile unsigned*)&g_sense;
        __threadfence();
        if (atomicAdd(&g_count, 1u) == NBLK - 1u) {
            g_count = 0;
            __threadfence();
            atomicExch(&g_sense, s + 1u);
        } else {
            while (*(volatile unsigned*)&g_sense == s) {}
        }
        __threadfence();
    }
    __syncthreads();
}

// ---------------- prep: tiled transpose into device scratch ----------------
__global__ void transpose_kernel(const float* __restrict__ src, int dst_sel,
                                 int rows, int cols) {
    float* dst = (dst_sel == 0) ? g_Wstk
               : (dst_sel == 1) ? (g_Wstk + NNEUR * NNEUR)
                                : g_WoutT;
    __shared__ float tile[32][33];
    int x = blockIdx.x * 32 + threadIdx.x;
    int y0 = blockIdx.y * 32;
#pragma unroll
    for (int j = 0; j < 32; j += 8) {
        int y = y0 + threadIdx.y + j;
        if (x < cols && y < rows)
            tile[threadIdx.y + j][threadIdx.x] = src[(size_t)y * cols + x];
    }
    __syncthreads();
    int xo = blockIdx.y * 32 + threadIdx.x;
    int yo0 = blockIdx.x * 32;
#pragma unroll
    for (int j = 0; j < 32; j += 8) {
        int yo = yo0 + threadIdx.y + j;
        if (xo < rows && yo < cols)
            dst[(size_t)yo * rows + xo] = tile[threadIdx.x][threadIdx.y + j];
    }
}

__global__ void zero_state_kernel() {
    int idx = blockIdx.x * blockDim.x + threadIdx.x;
    if (idx < BATCH * NNEUR) {
        g_vA[idx] = 0.0f;
        g_sA[idx] = 0.0f;
    }
}

__global__ void nop_kernel() {}

// ---------------- persistent time-loop kernel ----------------
// FROZEN numerics contract for the FEEDBACK path (bitwise-matched to ref):
//  * recurrent sum: split-K(2): k=[0,512),[512,1024), each ascending FMA
//    chain; combined P0 + P1 with one fp32 add.
//  * input projection: single ascending k=0..63 FMA chain.
//  * state update, no contraction: v' = (((0.9f*v) + accR) + accI) - s.
//  * spike: s' = (v' > 1.0f).  State reads via __ldcg (L2-coherent).
// This round: inner math via packed fma.rn.f32x2 (FFMA2) — per-element
// rounding and order identical, half the FMA-pipe instructions. Data staging
// reverted to R10's register double-buffer (cp.async regressed).
__global__ __launch_bounds__(128, 2) void lif_persistent(
        const float* __restrict__ inputs, float* __restrict__ out) {
    __shared__ __align__(16) float2 As[2][16][34];  // duplicated (a,a) pairs [stage][kk][b]
    __shared__ __align__(16) float  Bs[2][16][36];  // [stage][kk][i]  32 neurons
    __shared__ float sv[2][NNEUR];                  // out-phase v rows
    __shared__ float red[2][2][ACT];                // out-phase partials

    const int tid = threadIdx.x;
    const int tx = tid & 7;             // neuron groups (TN=4) -> 32 i
    const int ty = tid >> 3;            // batch pairs  (TM=2) -> 32 b
    const int bi0 = (blockIdx.x & 31) * 32;   // 32 neuron tiles
    const int bb0 = (blockIdx.x >> 5) * 32;   // 8 batch tiles

    const int lb = tid >> 3;            // A: batch 0..15 (+16 second row)
    const int lk = (tid & 7) * 2;       // A: k pair
    const int wk = tid >> 3;            // B: k 0..15
    const int wi = (tid & 7) * 4;       // B: neuron quad

    for (int t = 0; t < SEQLEN; ++t) {
        const float* __restrict__ vIn  = (t & 1) ? g_vB : g_vA;
        float* __restrict__       vOut = (t & 1) ? g_vA : g_vB;
        const float* __restrict__ sIn  = (t & 1) ? g_sB : g_sA;
        float* __restrict__       sOut = (t & 1) ? g_sA : g_sB;

        const float* sRow0 = &sIn[(bb0 + lb) * NNEUR + lk];
        const float* sRow1 = &sIn[(bb0 + lb + 16) * NNEUR + lk];

        // ======== phase A1: recurrent GEMM (64 blocks, double-buffered) ========
        // accP2[m][np]: f32x2 pair over neurons (2np, 2np+1) for batch row m.
        unsigned long long accP2[2][2] = {{0ull, 0ull}, {0ull, 0ull}};
        unsigned long long accQ2[2][2];

        float2 av0 = __ldcg(reinterpret_cast<const float2*>(sRow0));
        float2 av1 = __ldcg(reinterpret_cast<const float2*>(sRow1));
        float4 bv = *reinterpret_cast<const float4*>(
                        &g_Wstk[(size_t)wk * NNEUR + bi0 + wi]);
        As[0][lk][lb] = make_float2(av0.x, av0.x);
        As[0][lk + 1][lb] = make_float2(av0.y, av0.y);
        As[0][lk][lb + 16] = make_float2(av1.x, av1.x);
        As[0][lk + 1][lb + 16] = make_float2(av1.y, av1.y);
        *reinterpret_cast<float4*>(&Bs[0][wk][wi]) = bv;

        for (int blk = 0; blk < 64; ++blk) {
            const int st = blk & 1;
            __syncthreads();                      // stage st ready
            if (blk < 63) {
                const int kn = (blk + 1) * 16;
                av0 = __ldcg(reinterpret_cast<const float2*>(sRow0 + kn));
                av1 = __ldcg(reinterpret_cast<const float2*>(sRow1 + kn));
                bv = *reinterpret_cast<const float4*>(
                        &g_Wstk[(size_t)(kn + wk) * NNEUR + bi0 + wi]);
            }
            if (blk == 32) {                      // split-K(2) boundary at k=512
#pragma unroll
                for (int m = 0; m < 2; ++m)
#pragma unroll
                    for (int np = 0; np < 2; ++np) {
                        accQ2[m][np] = accP2[m][np];
                        accP2[m][np] = 0ull;
                    }
            }
#pragma unroll
            for (int kk = 0; kk < 16; ++kk) {
                // a: both duplicated batch pairs in one 16B load
                ulonglong2 ap = *reinterpret_cast<const ulonglong2*>(&As[st][kk][ty * 2]);
                // b: two adjacent-neuron pairs in one 16B load
                ulonglong2 bp = *reinterpret_cast<const ulonglong2*>(&Bs[st][kk][tx * 4]);
                fma2(accP2[0][0], ap.x, bp.x);
                fma2(accP2[0][1], ap.x, bp.y);
                fma2(accP2[1][0], ap.y, bp.x);
                fma2(accP2[1][1], ap.y, bp.y);
            }
            if (blk < 63) {
                const int sn = st ^ 1;
                As[sn][lk][lb] = make_float2(av0.x, av0.x);
                As[sn][lk + 1][lb] = make_float2(av0.y, av0.y);
                As[sn][lk][lb + 16] = make_float2(av1.x, av1.x);
                As[sn][lk + 1][lb + 16] = make_float2(av1.y, av1.y);
                *reinterpret_cast<float4*>(&Bs[sn][wk][wi]) = bv;
            }
        }
        unsigned long long accS2[2][2];
#pragma unroll
        for (int m = 0; m < 2; ++m)
#pragma unroll
            for (int np = 0; np < 2; ++np)
                accS2[m][np] = add2(accQ2[m][np], accP2[m][np]);  // P0 + P1

        // ======== phase A2: input projection (4 blocks, ascending chain) ========
        unsigned long long accI2[2][2] = {{0ull, 0ull}, {0ull, 0ull}};
        {
            const size_t ib0 = ((size_t)(bb0 + lb) * SEQLEN + t) * OBS;
            const size_t ib1 = ((size_t)(bb0 + lb + 16) * SEQLEN + t) * OBS;
            av0 = *reinterpret_cast<const float2*>(&inputs[ib0 + lk]);
            av1 = *reinterpret_cast<const float2*>(&inputs[ib1 + lk]);
            bv = *reinterpret_cast<const float4*>(
                    &g_Wstk[(size_t)(NNEUR + wk) * NNEUR + bi0 + wi]);
            // stage 0 safe: all threads passed blk-63's __syncthreads
            As[0][lk][lb] = make_float2(av0.x, av0.x);
            As[0][lk + 1][lb] = make_float2(av0.y, av0.y);
            As[0][lk][lb + 16] = make_float2(av1.x, av1.x);
            As[0][lk + 1][lb + 16] = make_float2(av1.y, av1.y);
            *reinterpret_cast<float4*>(&Bs[0][wk][wi]) = bv;
#pragma unroll
            for (int blk = 0; blk < 4; ++blk) {
                const int st = blk & 1;
                __syncthreads();
                if (blk < 3) {
                    const int kc = (blk + 1) * 16;
                    av0 = *reinterpret_cast<const float2*>(&inputs[ib0 + kc + lk]);
                    av1 = *reinterpret_cast<const float2*>(&inputs[ib1 + kc + lk]);
                    bv = *reinterpret_cast<const float4*>(
                            &g_Wstk[(size_t)(NNEUR + kc + wk) * NNEUR + bi0 + wi]);
                }
#pragma unroll
                for (int kk = 0; kk < 16; ++kk) {
                    ulonglong2 ap = *reinterpret_cast<const ulonglong2*>(&As[st][kk][ty * 2]);
                    ulonglong2 bp = *reinterpret_cast<const ulonglong2*>(&Bs[st][kk][tx * 4]);
                    fma2(accI2[0][0], ap.x, bp.x);
                    fma2(accI2[0][1], ap.x, bp.y);
                    fma2(accI2[1][0], ap.y, bp.x);
                    fma2(accI2[1][1], ap.y, bp.y);
                }
                if (blk < 3) {
                    const int sn = st ^ 1;
                    As[sn][lk][lb] = make_float2(av0.x, av0.x);
                    As[sn][lk + 1][lb] = make_float2(av0.y, av0.y);
                    As[sn][lk][lb + 16] = make_float2(av1.x, av1.x);
                    As[sn][lk + 1][lb + 16] = make_float2(av1.y, av1.y);
                    *reinterpret_cast<float4*>(&Bs[sn][wk][wi]) = bv;
                }
            }
        }

        // ---- epilogue: v' = (((0.9*v) + accS) + accI) - s  — strictly NO fma ----
#pragma unroll
        for (int m = 0; m < 2; ++m) {
            int b = bb0 + ty * 2 + m;
#pragma unroll
            for (int np = 0; np < 2; ++np) {
                F2U ur, ui;
                ur.u = accS2[m][np];
                ui.u = accI2[m][np];
#pragma unroll
                for (int j = 0; j < 2; ++j) {
                    int i = bi0 + tx * 4 + np * 2 + j;
                    int idx = b * NNEUR + i;
                    float aR = j ? ur.f.y : ur.f.x;
                    float aI = j ? ui.f.y : ui.f.x;
                    float so = __ldcg(&sIn[idx]);
                    float vl = __ldcg(&vIn[idx]);
                    float leak = __fmul_rn(BETA_C, vl);
                    float v = __fsub_rn(__fadd_rn(__fadd_rn(leak, aR), aI), so);
                    vOut[idx] = v;
                    sOut[idx] = (v > VTH_C) ? 1.0f : 0.0f;
                }
            }
        }

        grid_barrier();

        // ======== phase B: action head on CTAs 0..127 (2 rows each) ========
        // Non-feedback -> free ordering. CTAs 128..255 proceed straight to the
        // next step's GEMM (opposite-parity state buffers; no hazard).
        if (blockIdx.x < 128) {
            const int r0 = blockIdx.x * 2;
            const float4* vs = reinterpret_cast<const float4*>(&vOut[(size_t)r0 * NNEUR]);
            float4* dstv = reinterpret_cast<float4*>(&sv[0][0]);
#pragma unroll
            for (int i = 0; i < 4; ++i)
                dstv[tid + i * 128] = __ldcg(&vs[tid + i * 128]);
            __syncthreads();

            const int a = tid & 63;
            const int h = tid >> 6;             // k-half
            const int kb = h * 512;
            float x0 = 0.f, x1 = 0.f;
#pragma unroll 8
            for (int k = 0; k < 512; ++k) {
                float w = g_WoutT[(size_t)(kb + k) * ACT + a];
                x0 = __fmaf_rn(sv[0][kb + k], w, x0);
                x1 = __fmaf_rn(sv[1][kb + k], w, x1);
            }
            red[h][0][a] = x0;
            red[h][1][a] = x1;
            __syncthreads();

            const int rr = tid >> 6;            // row 0/1
            const int aa = tid & 63;
            float s2 = __fadd_rn(red[0][rr][aa], red[1][rr][aa]);
            out[((size_t)(r0 + rr) * SEQLEN + t) * ACT + aa] = tanhf(s2);
            // sv/red reused only after the NEXT grid_barrier + __syncthreads.
        }
    }
}

// ---------------- launch ----------------
extern "C" void kernel_launch(void* const* d_in, const int* in_sizes, int n_in,
                              void* d_out, int out_size) {
    const float* inputs = (const float*)d_in[0];   // (B, T, OBS)
    const float* W_rec  = (const float*)d_in[1];   // (N, N)
    const float* W_in   = (const float*)d_in[2];   // (N, OBS)
    const float* W_out  = (const float*)d_in[3];   // (ACT, N)
    float* out = (float*)d_out;                    // (B, T, ACT)

    dim3 tb(32, 8);
    transpose_kernel<<<dim3(NNEUR / 32, NNEUR / 32), tb>>>(W_rec, 0, NNEUR, NNEUR);
    transpose_kernel<<<dim3(OBS / 32, NNEUR / 32), tb>>>(W_in, 1, NNEUR, OBS);
    transpose_kernel<<<dim3(NNEUR / 32, ACT / 32), tb>>>(W_out, 2, ACT, NNEUR);
    zero_state_kernel<<<(BATCH * NNEUR) / 256, 256>>>();
    nop_kernel<<<1, 32>>>();

    lif_persistent<<<NBLK, 128>>>(inputs, out);
}

// round 14
// speedup vs baseline: 1.4331x; 1.4331x over previous
#include <cuda_runtime.h>
#include <math.h>

// Problem constants
#define BATCH 256
#define SEQLEN 512
#define OBS 64
#define NNEUR 1024
#define ACT 64
#define KTOT (NNEUR + OBS)
#define NBLK 128             // persistent CTAs: 1/SM (128 <= 148), all co-resident

#define BETA_C 0.9f
#define VTH_C 1.0f

// ---------------- device scratch (static; no allocations) ----------------
__device__ float g_Wstk[KTOT * NNEUR];    // rows 0..1023: W_rec.T ; rows 1024..1087: W_in.T
__device__ float g_WoutT[NNEUR * ACT];    // (k, a)
__device__ float g_vA[BATCH * NNEUR];
__device__ float g_vB[BATCH * NNEUR];
__device__ float g_sA[BATCH * NNEUR];
__device__ float g_sB[BATCH * NNEUR];
__device__ unsigned g_count = 0;
__device__ unsigned g_sense = 0;          // monotonic phase; replay-safe

// ---------------- software grid barrier (NBLK co-resident CTAs) ----------------
__device__ __forceinline__ void grid_barrier() {
    __syncthreads();
    if (threadIdx.x == 0) {
        unsigned s = *(volatile unsigned*)&g_sense;
        __threadfence();
        if (atomicAdd(&g_count, 1u) == NBLK - 1u) {
            g_count = 0;
            __threadfence();
            atomicExch(&g_sense, s + 1u);
        } else {
            while (*(volatile unsigned*)&g_sense == s) {}
        }
        __threadfence();
    }
    __syncthreads();
}

// ---------------- prep: tiled transpose into device scratch ----------------
__global__ void transpose_kernel(const float* __restrict__ src, int dst_sel,
                                 int rows, int cols) {
    float* dst = (dst_sel == 0) ? g_Wstk
               : (dst_sel == 1) ? (g_Wstk + NNEUR * NNEUR)
                                : g_WoutT;
    __shared__ float tile[32][33];
    int x = blockIdx.x * 32 + threadIdx.x;
    int y0 = blockIdx.y * 32;
#pragma unroll
    for (int j = 0; j < 32; j += 8) {
        int y = y0 + threadIdx.y + j;
        if (x < cols && y < rows)
            tile[threadIdx.y + j][threadIdx.x] = src[(size_t)y * cols + x];
    }
    __syncthreads();
    int xo = blockIdx.y * 32 + threadIdx.x;
    int yo0 = blockIdx.x * 32;
#pragma unroll
    for (int j = 0; j < 32; j += 8) {
        int yo = yo0 + threadIdx.y + j;
        if (xo < rows && yo < cols)
            dst[(size_t)yo * rows + xo] = tile[threadIdx.x][threadIdx.y + j];
    }
}

__global__ void zero_state_kernel() {
    int idx = blockIdx.x * blockDim.x + threadIdx.x;
    if (idx < BATCH * NNEUR) {
        g_vA[idx] = 0.0f;
        g_sA[idx] = 0.0f;
    }
}

__global__ void nop_kernel() {}

// ---------------- persistent time-loop kernel ----------------
// FROZEN numerics contract for the FEEDBACK path (bitwise-matched to ref):
//  * recurrent sum: split-K(2): k=[0,512),[512,1024), each ascending FMA
//    chain; combined P0 + P1 with one __fadd_rn. (Chain order is independent
//    of the tiling — only the per-accumulator k order matters.)
//  * input projection: single ascending k=0..63 FMA chain.
//  * state update, no contraction: v' = (((0.9f*v) + accR) + accI) - s.
//  * spike: s' = (v' > 1.0f).  State reads via __ldcg (L2-coherent).
// This round: TM4xTN4 register tile (smem crossbar was the binding resource:
// 48 cyc/kk/SM before, ~12 now; FMA pipe becomes the bound).
__global__ __launch_bounds__(128, 1) void lif_persistent(
        const float* __restrict__ inputs, float* __restrict__ out) {
    __shared__ __align__(16) float As[2][16][36];  // [stage][kk][row]  32 rows, 144B stride
    __shared__ __align__(16) float Bs[2][16][68];  // [stage][kk][col]  64 cols, 272B stride
    __shared__ float sv[2][NNEUR];                 // head v rows
    __shared__ float red[2][2][ACT];               // head partials

    const int tid = threadIdx.x;
    const int tx = tid & 15;            // neuron group (TN=4) -> 64 neurons
    const int ty = tid >> 4;            // row group   (TM=4) -> 32 rows
    const int bi0 = (blockIdx.x & 15) * 64;   // 16 column tiles
    const int bb0 = (blockIdx.x >> 4) * 32;   // 8 row tiles  -> grid 128

    const int al_row = tid >> 2;        // A loader: row 0..31
    const int al_k   = (tid & 3) * 4;   // A loader: k offset 0,4,8,12
    const int bl_k   = tid >> 3;        // B loader: kk 0..15
    const int bl_n   = (tid & 7) * 8;   // B loader: col offset (2 float4)

    for (int t = 0; t < SEQLEN; ++t) {
        const float* __restrict__ vIn  = (t & 1) ? g_vB : g_vA;
        float* __restrict__       vOut = (t & 1) ? g_vA : g_vB;
        const float* __restrict__ sIn  = (t & 1) ? g_sB : g_sA;
        float* __restrict__       sOut = (t & 1) ? g_sA : g_sB;

        const float* aRow = &sIn[(bb0 + al_row) * NNEUR + al_k];
        const float* wRow0 = &g_Wstk[(size_t)bl_k * NNEUR + bi0 + bl_n];

        // ---- prologue: stage 0 ----
        {
            float4 a4 = __ldcg(reinterpret_cast<const float4*>(aRow));
            float4 b0 = *reinterpret_cast<const float4*>(wRow0);
            float4 b1 = *reinterpret_cast<const float4*>(wRow0 + 4);
            As[0][al_k][al_row] = a4.x;     As[0][al_k + 1][al_row] = a4.y;
            As[0][al_k + 2][al_row] = a4.z; As[0][al_k + 3][al_row] = a4.w;
            *reinterpret_cast<float4*>(&Bs[0][bl_k][bl_n]) = b0;
            *reinterpret_cast<float4*>(&Bs[0][bl_k][bl_n + 4]) = b1;
        }

        // ======== phase A1: recurrent GEMM (64 blocks, double-buffered) ========
        float accP[4][4], accQ[4][4];
#pragma unroll
        for (int m = 0; m < 4; ++m)
#pragma unroll
            for (int n = 0; n < 4; ++n) accP[m][n] = 0.0f;

        float4 a4n, b0n, b1n;
        for (int blk = 0; blk < 64; ++blk) {
            const int st = blk & 1;
            __syncthreads();                      // stage st ready
            if (blk < 63) {
                const int kn = (blk + 1) * 16;
                a4n = __ldcg(reinterpret_cast<const float4*>(aRow + kn));
                b0n = *reinterpret_cast<const float4*>(wRow0 + (size_t)kn * NNEUR);
                b1n = *reinterpret_cast<const float4*>(wRow0 + (size_t)kn * NNEUR + 4);
            }
            if (blk == 32) {                      // split-K(2) boundary at k=512
#pragma unroll
                for (int m = 0; m < 4; ++m)
#pragma unroll
                    for (int n = 0; n < 4; ++n) {
                        accQ[m][n] = accP[m][n];
                        accP[m][n] = 0.0f;
                    }
            }
#pragma unroll
            for (int kk = 0; kk < 16; ++kk) {
                float4 a = *reinterpret_cast<const float4*>(&As[st][kk][ty * 4]);
                float4 b = *reinterpret_cast<const float4*>(&Bs[st][kk][tx * 4]);
                accP[0][0] = __fmaf_rn(a.x, b.x, accP[0][0]);
                accP[0][1] = __fmaf_rn(a.x, b.y, accP[0][1]);
                accP[0][2] = __fmaf_rn(a.x, b.z, accP[0][2]);
                accP[0][3] = __fmaf_rn(a.x, b.w, accP[0][3]);
                accP[1][0] = __fmaf_rn(a.y, b.x, accP[1][0]);
                accP[1][1] = __fmaf_rn(a.y, b.y, accP[1][1]);
                accP[1][2] = __fmaf_rn(a.y, b.z, accP[1][2]);
                accP[1][3] = __fmaf_rn(a.y, b.w, accP[1][3]);
                accP[2][0] = __fmaf_rn(a.z, b.x, accP[2][0]);
                accP[2][1] = __fmaf_rn(a.z, b.y, accP[2][1]);
                accP[2][2] = __fmaf_rn(a.z, b.z, accP[2][2]);
                accP[2][3] = __fmaf_rn(a.z, b.w, accP[2][3]);
                accP[3][0] = __fmaf_rn(a.w, b.x, accP[3][0]);
                accP[3][1] = __fmaf_rn(a.w, b.y, accP[3][1]);
                accP[3][2] = __fmaf_rn(a.w, b.z, accP[3][2]);
                accP[3][3] = __fmaf_rn(a.w, b.w, accP[3][3]);
            }
            if (blk < 63) {
                const int sn = st ^ 1;
                As[sn][al_k][al_row] = a4n.x;     As[sn][al_k + 1][al_row] = a4n.y;
                As[sn][al_k + 2][al_row] = a4n.z; As[sn][al_k + 3][al_row] = a4n.w;
                *reinterpret_cast<float4*>(&Bs[sn][bl_k][bl_n]) = b0n;
                *reinterpret_cast<float4*>(&Bs[sn][bl_k][bl_n + 4]) = b1n;
            }
        }
        float accS[4][4];
#pragma unroll
        for (int m = 0; m < 4; ++m)
#pragma unroll
            for (int n = 0; n < 4; ++n)
                accS[m][n] = __fadd_rn(accQ[m][n], accP[m][n]);  // P0 + P1

        // ======== phase A2: input projection (4 blocks, ascending chain) ========
        float accI[4][4];
#pragma unroll
        for (int m = 0; m < 4; ++m)
#pragma unroll
            for (int n = 0; n < 4; ++n) accI[m][n] = 0.0f;
        {
            const float* iRow = &inputs[((size_t)(bb0 + al_row) * SEQLEN + t) * OBS + al_k];
            const float* wRowI = &g_Wstk[(size_t)(NNEUR + bl_k) * NNEUR + bi0 + bl_n];
            // stage 0 safe: all threads passed blk-63's top __syncthreads
            {
                float4 a4 = *reinterpret_cast<const float4*>(iRow);
                float4 b0 = *reinterpret_cast<const float4*>(wRowI);
                float4 b1 = *reinterpret_cast<const float4*>(wRowI + 4);
                As[0][al_k][al_row] = a4.x;     As[0][al_k + 1][al_row] = a4.y;
                As[0][al_k + 2][al_row] = a4.z; As[0][al_k + 3][al_row] = a4.w;
                *reinterpret_cast<float4*>(&Bs[0][bl_k][bl_n]) = b0;
                *reinterpret_cast<float4*>(&Bs[0][bl_k][bl_n + 4]) = b1;
            }
#pragma unroll
            for (int blk = 0; blk < 4; ++blk) {
                const int st = blk & 1;
                __syncthreads();
                if (blk < 3) {
                    const int kc = (blk + 1) * 16;
                    a4n = *reinterpret_cast<const float4*>(iRow + kc);
                    b0n = *reinterpret_cast<const float4*>(wRowI + (size_t)kc * NNEUR);
                    b1n = *reinterpret_cast<const float4*>(wRowI + (size_t)kc * NNEUR + 4);
                }
#pragma unroll
                for (int kk = 0; kk < 16; ++kk) {
                    float4 a = *reinterpret_cast<const float4*>(&As[st][kk][ty * 4]);
                    float4 b = *reinterpret_cast<const float4*>(&Bs[st][kk][tx * 4]);
                    accI[0][0] = __fmaf_rn(a.x, b.x, accI[0][0]);
                    accI[0][1] = __fmaf_rn(a.x, b.y, accI[0][1]);
                    accI[0][2] = __fmaf_rn(a.x, b.z, accI[0][2]);
                    accI[0][3] = __fmaf_rn(a.x, b.w, accI[0][3]);
                    accI[1][0] = __fmaf_rn(a.y, b.x, accI[1][0]);
                    accI[1][1] = __fmaf_rn(a.y, b.y, accI[1][1]);
                    accI[1][2] = __fmaf_rn(a.y, b.z, accI[1][2]);
                    accI[1][3] = __fmaf_rn(a.y, b.w, accI[1][3]);
                    accI[2][0] = __fmaf_rn(a.z, b.x, accI[2][0]);
                    accI[2][1] = __fmaf_rn(a.z, b.y, accI[2][1]);
                    accI[2][2] = __fmaf_rn(a.z, b.z, accI[2][2]);
                    accI[2][3] = __fmaf_rn(a.z, b.w, accI[2][3]);
                    accI[3][0] = __fmaf_rn(a.w, b.x, accI[3][0]);
                    accI[3][1] = __fmaf_rn(a.w, b.y, accI[3][1]);
                    accI[3][2] = __fmaf_rn(a.w, b.z, accI[3][2]);
                    accI[3][3] = __fmaf_rn(a.w, b.w, accI[3][3]);
                }
                if (blk < 3) {
                    const int sn = st ^ 1;
                    As[sn][al_k][al_row] = a4n.x;     As[sn][al_k + 1][al_row] = a4n.y;
                    As[sn][al_k + 2][al_row] = a4n.z; As[sn][al_k + 3][al_row] = a4n.w;
                    *reinterpret_cast<float4*>(&Bs[sn][bl_k][bl_n]) = b0n;
                    *reinterpret_cast<float4*>(&Bs[sn][bl_k][bl_n + 4]) = b1n;
                }
            }
        }

        // ---- epilogue: v' = (((0.9*v) + accS) + accI) - s  — strictly NO fma ----
#pragma unroll
        for (int m = 0; m < 4; ++m) {
            int b = bb0 + ty * 4 + m;
            int idx = b * NNEUR + bi0 + tx * 4;
            float4 so4 = __ldcg(reinterpret_cast<const float4*>(&sIn[idx]));
            float4 vl4 = __ldcg(reinterpret_cast<const float4*>(&vIn[idx]));
            float4 vo, sp;
            {
                float v0 = __fsub_rn(__fadd_rn(__fadd_rn(__fmul_rn(BETA_C, vl4.x), accS[m][0]), accI[m][0]), so4.x);
                float v1 = __fsub_rn(__fadd_rn(__fadd_rn(__fmul_rn(BETA_C, vl4.y), accS[m][1]), accI[m][1]), so4.y);
                float v2 = __fsub_rn(__fadd_rn(__fadd_rn(__fmul_rn(BETA_C, vl4.z), accS[m][2]), accI[m][2]), so4.z);
                float v3 = __fsub_rn(__fadd_rn(__fadd_rn(__fmul_rn(BETA_C, vl4.w), accS[m][3]), accI[m][3]), so4.w);
                vo = make_float4(v0, v1, v2, v3);
                sp = make_float4(v0 > VTH_C ? 1.0f : 0.0f, v1 > VTH_C ? 1.0f : 0.0f,
                                 v2 > VTH_C ? 1.0f : 0.0f, v3 > VTH_C ? 1.0f : 0.0f);
            }
            *reinterpret_cast<float4*>(&vOut[idx]) = vo;
            *reinterpret_cast<float4*>(&sOut[idx]) = sp;
        }

        grid_barrier();

        // ======== phase B: action head, all 128 CTAs, 2 rows each ========
        // Non-feedback -> free ordering (split-k(2) + tree combine).
        {
            const int r0 = blockIdx.x * 2;
            const float4* vs = reinterpret_cast<const float4*>(&vOut[(size_t)r0 * NNEUR]);
            float4* dstv = reinterpret_cast<float4*>(&sv[0][0]);
#pragma unroll
            for (int i = 0; i < 4; ++i)
                dstv[tid + i * 128] = __ldcg(&vs[tid + i * 128]);
            __syncthreads();

            const int a = tid & 63;
            const int h = tid >> 6;             // k-half
            const int kb = h * 512;
            float x0 = 0.f, x1 = 0.f;
#pragma unroll 8
            for (int k = 0; k < 512; ++k) {
                float w = g_WoutT[(size_t)(kb + k) * ACT + a];
                x0 = __fmaf_rn(sv[0][kb + k], w, x0);
                x1 = __fmaf_rn(sv[1][kb + k], w, x1);
            }
            red[h][0][a] = x0;
            red[h][1][a] = x1;
            __syncthreads();

            const int rr = tid >> 6;            // row 0/1
            const int aa = tid & 63;
            float s2 = __fadd_rn(red[0][rr][aa], red[1][rr][aa]);
            out[((size_t)(r0 + rr) * SEQLEN + t) * ACT + aa] = tanhf(s2);
            // sv/red reused only after the NEXT grid_barrier + __syncthreads.
        }
    }
}

// ---------------- launch ----------------
extern "C" void kernel_launch(void* const* d_in, const int* in_sizes, int n_in,
                              void* d_out, int out_size) {
    const float* inputs = (const float*)d_in[0];   // (B, T, OBS)
    const float* W_rec  = (const float*)d_in[1];   // (N, N)
    const float* W_in   = (const float*)d_in[2];   // (N, OBS)
    const float* W_out  = (const float*)d_in[3];   // (ACT, N)
    float* out = (float*)d_out;                    // (B, T, ACT)

    dim3 tb(32, 8);
    transpose_kernel<<<dim3(NNEUR / 32, NNEUR / 32), tb>>>(W_rec, 0, NNEUR, NNEUR);
    transpose_kernel<<<dim3(OBS / 32, NNEUR / 32), tb>>>(W_in, 1, NNEUR, OBS);
    transpose_kernel<<<dim3(NNEUR / 32, ACT / 32), tb>>>(W_out, 2, ACT, NNEUR);
    zero_state_kernel<<<(BATCH * NNEUR) / 256, 256>>>();
    nop_kernel<<<1, 32>>>();

    lif_persistent<<<NBLK, 128>>>(inputs, out);
}

// round 16
// speedup vs baseline: 1.7691x; 1.2345x over previous
#include <cuda_runtime.h>
#include <math.h>

// Problem constants
#define BATCH 256
#define SEQLEN 512
#define OBS 64
#define NNEUR 1024
#define ACT 64
#define KTOT (NNEUR + OBS)
#define NBLK 128             // persistent CTAs: 1/SM (128 <= 148), all co-resident

#define BETA_C 0.9f
#define VTH_C 1.0f
#define VPAD 1028            // padded row stride (floats) for head smem arrays

// ---------------- device scratch (static; no allocations) ----------------
__device__ float g_Wstk[KTOT * NNEUR];    // rows 0..1023: W_rec.T ; rows 1024..1087: W_in.T
__device__ float g_WoutT[NNEUR * ACT];    // (k, a)
__device__ float g_vA[BATCH * NNEUR];
__device__ float g_vB[BATCH * NNEUR];
__device__ float g_sA[BATCH * NNEUR];
__device__ float g_sB[BATCH * NNEUR];
__device__ unsigned g_count = 0;
__device__ unsigned g_sense = 0;          // monotonic phase; replay-safe

// ---------------- dynamic smem layout (112,000 B < 227 KB opt-in) ----------------
struct __align__(16) Smem {
    float As[2][16][36];     // GEMM A tiles
    float Bs[2][16][68];     // GEMM B tiles
    float w_s[16][VPAD];     // head: W_out slice [local_a][k], persistent
    float v_s[8][VPAD];      // head: v rows, staged per step
};
#define SMEM_BYTES ((int)sizeof(Smem))

// ---------------- software grid barrier (NBLK co-resident CTAs) ----------------
__device__ __forceinline__ void grid_barrier() {
    __syncthreads();
    if (threadIdx.x == 0) {
        unsigned s = *(volatile unsigned*)&g_sense;
        __threadfence();
        if (atomicAdd(&g_count, 1u) == NBLK - 1u) {
            g_count = 0;
            __threadfence();
            atomicExch(&g_sense, s + 1u);
        } else {
            while (*(volatile unsigned*)&g_sense == s) {}
        }
        __threadfence();
    }
    __syncthreads();
}

// ---------------- prep: tiled transpose into device scratch ----------------
__global__ void transpose_kernel(const float* __restrict__ src, int dst_sel,
                                 int rows, int cols) {
    float* dst = (dst_sel == 0) ? g_Wstk
               : (dst_sel == 1) ? (g_Wstk + NNEUR * NNEUR)
                                : g_WoutT;
    __shared__ float tile[32][33];
    int x = blockIdx.x * 32 + threadIdx.x;
    int y0 = blockIdx.y * 32;
#pragma unroll
    for (int j = 0; j < 32; j += 8) {
        int y = y0 + threadIdx.y + j;
        if (x < cols && y < rows)
            tile[threadIdx.y + j][threadIdx.x] = src[(size_t)y * cols + x];
    }
    __syncthreads();
    int xo = blockIdx.y * 32 + threadIdx.x;
    int yo0 = blockIdx.x * 32;
#pragma unroll
    for (int j = 0; j < 32; j += 8) {
        int yo = yo0 + threadIdx.y + j;
        if (xo < rows && yo < cols)
            dst[(size_t)yo * rows + xo] = tile[threadIdx.x][threadIdx.y + j];
    }
}

__global__ void zero_state_kernel() {
    int idx = blockIdx.x * blockDim.x + threadIdx.x;
    if (idx < BATCH * NNEUR) {
        g_vA[idx] = 0.0f;
        g_sA[idx] = 0.0f;
    }
}

__global__ void nop_kernel() {}

// ---------------- persistent time-loop kernel ----------------
// FROZEN numerics contract for the FEEDBACK path (bitwise-matched to ref):
//  * recurrent sum: split-K(2): k=[0,512),[512,1024), each ascending FMA
//    chain; combined P0 + P1 with one __fadd_rn.
//  * input projection: single ascending k=0..63 FMA chain.
//  * state update, no contraction: v' = (((0.9f*v) + accR) + accI) - s.
//  * spike: s' = (v' > 1.0f).  State reads via __ldcg (L2-coherent).
// A1/A2/epilogue identical to R14 (passing). This round: the (non-feedback,
// free-order) action head is smem-resident: each CTA caches a 16-action W_out
// slice (64 KB) once, stages 8 v rows per step, computes entirely from smem.
__global__ __launch_bounds__(128, 1) void lif_persistent(
        const float* __restrict__ inputs, float* __restrict__ out) {
    extern __shared__ Smem smem[];
    Smem* sm = smem;

    const int tid = threadIdx.x;
    const int tx = tid & 15;            // neuron group (TN=4) -> 64 neurons
    const int ty = tid >> 4;            // row group   (TM=4) -> 32 rows
    const int bi0 = (blockIdx.x & 15) * 64;   // 16 column tiles
    const int bb0 = (blockIdx.x >> 4) * 32;   // 8 row tiles  -> grid 128

    const int al_row = tid >> 2;        // A loader: row 0..31
    const int al_k   = (tid & 3) * 4;   // A loader: k offset 0,4,8,12
    const int bl_k   = tid >> 3;        // B loader: kk 0..15
    const int bl_n   = (tid & 7) * 8;   // B loader: col offset (2 float4)

    // head mapping: slice of 16 actions x 8 batch rows per CTA
    const int hslice = blockIdx.x & 3;        // action slice 0..3
    const int hr0 = (blockIdx.x >> 2) * 8;    // batch rows r0..r0+7
    const int ha = tid >> 3;                  // local action 0..15
    const int hr = tid & 7;                   // local row 0..7
    const int hga = hslice * 16 + ha;         // global action

    // ---- one-time: cache W_out slice into smem [local_a][k] ----
    for (int i = tid; i < 16 * NNEUR; i += 128) {
        int a = i >> 10;          // 0..15
        int k = i & 1023;
        sm->w_s[a][k] = g_WoutT[(size_t)k * ACT + hslice * 16 + a];
    }
    // published by the first __syncthreads in the t=0 prologue (before any use)

    for (int t = 0; t < SEQLEN; ++t) {
        const float* __restrict__ vIn  = (t & 1) ? g_vB : g_vA;
        float* __restrict__       vOut = (t & 1) ? g_vA : g_vB;
        const float* __restrict__ sIn  = (t & 1) ? g_sB : g_sA;
        float* __restrict__       sOut = (t & 1) ? g_sA : g_sB;

        const float* aRow = &sIn[(bb0 + al_row) * NNEUR + al_k];
        const float* wRow0 = &g_Wstk[(size_t)bl_k * NNEUR + bi0 + bl_n];

        // ---- prologue: stage 0 ----
        {
            float4 a4 = __ldcg(reinterpret_cast<const float4*>(aRow));
            float4 b0 = *reinterpret_cast<const float4*>(wRow0);
            float4 b1 = *reinterpret_cast<const float4*>(wRow0 + 4);
            __syncthreads();   // t=0: w_s load done; t>0: head v_s consumers done
            sm->As[0][al_k][al_row] = a4.x;     sm->As[0][al_k + 1][al_row] = a4.y;
            sm->As[0][al_k + 2][al_row] = a4.z; sm->As[0][al_k + 3][al_row] = a4.w;
            *reinterpret_cast<float4*>(&sm->Bs[0][bl_k][bl_n]) = b0;
            *reinterpret_cast<float4*>(&sm->Bs[0][bl_k][bl_n + 4]) = b1;
        }

        // ======== phase A1: recurrent GEMM (64 blocks, double-buffered) ========
        float accP[4][4], accQ[4][4];
#pragma unroll
        for (int m = 0; m < 4; ++m)
#pragma unroll
            for (int n = 0; n < 4; ++n) accP[m][n] = 0.0f;

        float4 a4n, b0n, b1n;
        for (int blk = 0; blk < 64; ++blk) {
            const int st = blk & 1;
            __syncthreads();                      // stage st ready
            if (blk < 63) {
                const int kn = (blk + 1) * 16;
                a4n = __ldcg(reinterpret_cast<const float4*>(aRow + kn));
                b0n = *reinterpret_cast<const float4*>(wRow0 + (size_t)kn * NNEUR);
                b1n = *reinterpret_cast<const float4*>(wRow0 + (size_t)kn * NNEUR + 4);
            }
            if (blk == 32) {                      // split-K(2) boundary at k=512
#pragma unroll
                for (int m = 0; m < 4; ++m)
#pragma unroll
                    for (int n = 0; n < 4; ++n) {
                        accQ[m][n] = accP[m][n];
                        accP[m][n] = 0.0f;
                    }
            }
#pragma unroll
            for (int kk = 0; kk < 16; ++kk) {
                float4 a = *reinterpret_cast<const float4*>(&sm->As[st][kk][ty * 4]);
                float4 b = *reinterpret_cast<const float4*>(&sm->Bs[st][kk][tx * 4]);
                accP[0][0] = __fmaf_rn(a.x, b.x, accP[0][0]);
                accP[0][1] = __fmaf_rn(a.x, b.y, accP[0][1]);
                accP[0][2] = __fmaf_rn(a.x, b.z, accP[0][2]);
                accP[0][3] = __fmaf_rn(a.x, b.w, accP[0][3]);
                accP[1][0] = __fmaf_rn(a.y, b.x, accP[1][0]);
                accP[1][1] = __fmaf_rn(a.y, b.y, accP[1][1]);
                accP[1][2] = __fmaf_rn(a.y, b.z, accP[1][2]);
                accP[1][3] = __fmaf_rn(a.y, b.w, accP[1][3]);
                accP[2][0] = __fmaf_rn(a.z, b.x, accP[2][0]);
                accP[2][1] = __fmaf_rn(a.z, b.y, accP[2][1]);
                accP[2][2] = __fmaf_rn(a.z, b.z, accP[2][2]);
                accP[2][3] = __fmaf_rn(a.z, b.w, accP[2][3]);
                accP[3][0] = __fmaf_rn(a.w, b.x, accP[3][0]);
                accP[3][1] = __fmaf_rn(a.w, b.y, accP[3][1]);
                accP[3][2] = __fmaf_rn(a.w, b.z, accP[3][2]);
                accP[3][3] = __fmaf_rn(a.w, b.w, accP[3][3]);
            }
            if (blk < 63) {
                const int sn = st ^ 1;
                sm->As[sn][al_k][al_row] = a4n.x;     sm->As[sn][al_k + 1][al_row] = a4n.y;
                sm->As[sn][al_k + 2][al_row] = a4n.z; sm->As[sn][al_k + 3][al_row] = a4n.w;
                *reinterpret_cast<float4*>(&sm->Bs[sn][bl_k][bl_n]) = b0n;
                *reinterpret_cast<float4*>(&sm->Bs[sn][bl_k][bl_n + 4]) = b1n;
            }
        }
        float accS[4][4];
#pragma unroll
        for (int m = 0; m < 4; ++m)
#pragma unroll
            for (int n = 0; n < 4; ++n)
                accS[m][n] = __fadd_rn(accQ[m][n], accP[m][n]);  // P0 + P1

        // ======== phase A2: input projection (4 blocks, ascending chain) ========
        float accI[4][4];
#pragma unroll
        for (int m = 0; m < 4; ++m)
#pragma unroll
            for (int n = 0; n < 4; ++n) accI[m][n] = 0.0f;
        {
            const float* iRow = &inputs[((size_t)(bb0 + al_row) * SEQLEN + t) * OBS + al_k];
            const float* wRowI = &g_Wstk[(size_t)(NNEUR + bl_k) * NNEUR + bi0 + bl_n];
            // stage 0 safe: all threads passed blk-63's top __syncthreads
            {
                float4 a4 = *reinterpret_cast<const float4*>(iRow);
                float4 b0 = *reinterpret_cast<const float4*>(wRowI);
                float4 b1 = *reinterpret_cast<const float4*>(wRowI + 4);
                sm->As[0][al_k][al_row] = a4.x;     sm->As[0][al_k + 1][al_row] = a4.y;
                sm->As[0][al_k + 2][al_row] = a4.z; sm->As[0][al_k + 3][al_row] = a4.w;
                *reinterpret_cast<float4*>(&sm->Bs[0][bl_k][bl_n]) = b0;
                *reinterpret_cast<float4*>(&sm->Bs[0][bl_k][bl_n + 4]) = b1;
            }
#pragma unroll
            for (int blk = 0; blk < 4; ++blk) {
                const int st = blk & 1;
                __syncthreads();
                if (blk < 3) {
                    const int kc = (blk + 1) * 16;
                    a4n = *reinterpret_cast<const float4*>(iRow + kc);
                    b0n = *reinterpret_cast<const float4*>(wRowI + (size_t)kc * NNEUR);
                    b1n = *reinterpret_cast<const float4*>(wRowI + (size_t)kc * NNEUR + 4);
                }
#pragma unroll
                for (int kk = 0; kk < 16; ++kk) {
                    float4 a = *reinterpret_cast<const float4*>(&sm->As[st][kk][ty * 4]);
                    float4 b = *reinterpret_cast<const float4*>(&sm->Bs[st][kk][tx * 4]);
                    accI[0][0] = __fmaf_rn(a.x, b.x, accI[0][0]);
                    accI[0][1] = __fmaf_rn(a.x, b.y, accI[0][1]);
                    accI[0][2] = __fmaf_rn(a.x, b.z, accI[0][2]);
                    accI[0][3] = __fmaf_rn(a.x, b.w, accI[0][3]);
                    accI[1][0] = __fmaf_rn(a.y, b.x, accI[1][0]);
                    accI[1][1] = __fmaf_rn(a.y, b.y, accI[1][1]);
                    accI[1][2] = __fmaf_rn(a.y, b.z, accI[1][2]);
                    accI[1][3] = __fmaf_rn(a.y, b.w, accI[1][3]);
                    accI[2][0] = __fmaf_rn(a.z, b.x, accI[2][0]);
                    accI[2][1] = __fmaf_rn(a.z, b.y, accI[2][1]);
                    accI[2][2] = __fmaf_rn(a.z, b.z, accI[2][2]);
                    accI[2][3] = __fmaf_rn(a.z, b.w, accI[2][3]);
                    accI[3][0] = __fmaf_rn(a.w, b.x, accI[3][0]);
                    accI[3][1] = __fmaf_rn(a.w, b.y, accI[3][1]);
                    accI[3][2] = __fmaf_rn(a.w, b.z, accI[3][2]);
                    accI[3][3] = __fmaf_rn(a.w, b.w, accI[3][3]);
                }
                if (blk < 3) {
                    const int sn = st ^ 1;
                    sm->As[sn][al_k][al_row] = a4n.x;     sm->As[sn][al_k + 1][al_row] = a4n.y;
                    sm->As[sn][al_k + 2][al_row] = a4n.z; sm->As[sn][al_k + 3][al_row] = a4n.w;
                    *reinterpret_cast<float4*>(&sm->Bs[sn][bl_k][bl_n]) = b0n;
                    *reinterpret_cast<float4*>(&sm->Bs[sn][bl_k][bl_n + 4]) = b1n;
                }
            }
        }

        // ---- epilogue: v' = (((0.9*v) + accS) + accI) - s  — strictly NO fma ----
#pragma unroll
        for (int m = 0; m < 4; ++m) {
            int b = bb0 + ty * 4 + m;
            int idx = b * NNEUR + bi0 + tx * 4;
            float4 so4 = __ldcg(reinterpret_cast<const float4*>(&sIn[idx]));
            float4 vl4 = __ldcg(reinterpret_cast<const float4*>(&vIn[idx]));
            float v0 = __fsub_rn(__fadd_rn(__fadd_rn(__fmul_rn(BETA_C, vl4.x), accS[m][0]), accI[m][0]), so4.x);
            float v1 = __fsub_rn(__fadd_rn(__fadd_rn(__fmul_rn(BETA_C, vl4.y), accS[m][1]), accI[m][1]), so4.y);
            float v2 = __fsub_rn(__fadd_rn(__fadd_rn(__fmul_rn(BETA_C, vl4.z), accS[m][2]), accI[m][2]), so4.z);
            float v3 = __fsub_rn(__fadd_rn(__fadd_rn(__fmul_rn(BETA_C, vl4.w), accS[m][3]), accI[m][3]), so4.w);
            *reinterpret_cast<float4*>(&vOut[idx]) = make_float4(v0, v1, v2, v3);
            *reinterpret_cast<float4*>(&sOut[idx]) =
                make_float4(v0 > VTH_C ? 1.0f : 0.0f, v1 > VTH_C ? 1.0f : 0.0f,
                            v2 > VTH_C ? 1.0f : 0.0f, v3 > VTH_C ? 1.0f : 0.0f);
        }

        grid_barrier();

        // ======== phase B: smem-resident action head ========
        // stage 8 v rows (coalesced __ldcg, 2048 float4)
        for (int i = tid; i < 2048; i += 128) {
            int row = i >> 8;             // 0..7
            int c4 = (i & 255) * 4;       // 0..1020
            float4 vv = __ldcg(reinterpret_cast<const float4*>(
                            &vOut[(size_t)(hr0 + row) * NNEUR + c4]));
            *reinterpret_cast<float4*>(&sm->v_s[row][c4]) = vv;
        }
        __syncthreads();

        {
            float px = 0.f, py = 0.f, pz = 0.f, pw = 0.f;  // 4 interleaved chains
#pragma unroll 8
            for (int ks = 0; ks < 256; ++ks) {
                float4 wv = *reinterpret_cast<const float4*>(&sm->w_s[ha][ks * 4]);
                float4 vv = *reinterpret_cast<const float4*>(&sm->v_s[hr][ks * 4]);
                px = __fmaf_rn(wv.x, vv.x, px);
                py = __fmaf_rn(wv.y, vv.y, py);
                pz = __fmaf_rn(wv.z, vv.z, pz);
                pw = __fmaf_rn(wv.w, vv.w, pw);
            }
            float acc = __fadd_rn(__fadd_rn(__fadd_rn(px, py), pz), pw);
            out[((size_t)(hr0 + hr) * SEQLEN + t) * ACT + hga] = tanhf(acc);
        }
        // v_s re-staged only after the NEXT grid_barrier; As/Bs disjoint -> the
        // sync at the top of the next step's prologue protects v_s consumers.
    }
}

// ---------------- launch ----------------
extern "C" void kernel_launch(void* const* d_in, const int* in_sizes, int n_in,
                              void* d_out, int out_size) {
    const float* inputs = (const float*)d_in[0];   // (B, T, OBS)
    const float* W_rec  = (const float*)d_in[1];   // (N, N)
    const float* W_in   = (const float*)d_in[2];   // (N, OBS)
    const float* W_out  = (const float*)d_in[3];   // (ACT, N)
    float* out = (float*)d_out;                    // (B, T, ACT)

    cudaFuncSetAttribute(lif_persistent,
                         cudaFuncAttributeMaxDynamicSharedMemorySize, SMEM_BYTES);

    dim3 tb(32, 8);
    transpose_kernel<<<dim3(NNEUR / 32, NNEUR / 32), tb>>>(W_rec, 0, NNEUR, NNEUR);
    transpose_kernel<<<dim3(OBS / 32, NNEUR / 32), tb>>>(W_in, 1, NNEUR, OBS);
    transpose_kernel<<<dim3(NNEUR / 32, ACT / 32), tb>>>(W_out, 2, ACT, NNEUR);
    zero_state_kernel<<<(BATCH * NNEUR) / 256, 256>>>();
    nop_kernel<<<1, 32>>>();

    lif_persistent<<<NBLK, 128, SMEM_BYTES>>>(inputs, out);
}

// round 17
// speedup vs baseline: 1.8868x; 1.0665x over previous
#include <cuda_runtime.h>
#include <math.h>

// Problem constants
#define BATCH 256
#define SEQLEN 512
#define OBS 64
#define NNEUR 1024
#define ACT 64
#define KTOT (NNEUR + OBS)
#define NGEMM 128            // GEMM CTAs (tile 32 rows x 64 neurons)
#define NHEAD 16             // dedicated head CTAs (16 batch rows each)
#define NBLK (NGEMM + NHEAD) // 144 <= 148 SMs, all co-resident

#define BETA_C 0.9f
#define VTH_C 1.0f
#define VPAD 1032            // padded row stride (floats) for head v_s

// ---------------- device scratch (static; no allocations) ----------------
__device__ float g_Wstk[KTOT * NNEUR];    // rows 0..1023: W_rec.T ; rows 1024..1087: W_in.T
__device__ float g_WoutT[NNEUR * ACT];    // (k, a)
__device__ float g_vA[BATCH * NNEUR];
__device__ float g_vB[BATCH * NNEUR];
__device__ float g_sA[BATCH * NNEUR];
__device__ float g_sB[BATCH * NNEUR];
__device__ unsigned g_count = 0;
__device__ unsigned g_sense = 0;          // monotonic phase; replay-safe

// ---------------- dynamic smem layouts (union by CTA role) ----------------
struct __align__(16) SmemG {              // GEMM CTAs: 26.6 KB
    float As[2][32][36];
    float Bs[2][32][68];
};
struct __align__(16) SmemH {              // head CTAs: ~70 KB
    float v_s[16][VPAD];
    float red[16][ACT];
};
#define SMEM_BYTES ((int)(sizeof(SmemH) > sizeof(SmemG) ? sizeof(SmemH) : sizeof(SmemG)))

// ---------------- software grid barrier (NBLK co-resident CTAs) ----------------
// Consumer side needs no fence: all cross-CTA data reads after the barrier go
// through __ldcg (L2-direct) or volatile; only the producer release fence stays.
__device__ __forceinline__ void grid_barrier() {
    __syncthreads();
    if (threadIdx.x == 0) {
        unsigned s = *(volatile unsigned*)&g_sense;
        __threadfence();                          // release our stores to L2
        if (atomicAdd(&g_count, 1u) == NBLK - 1u) {
            g_count = 0;
            __threadfence();                      // reset visible before flip
            atomicExch(&g_sense, s + 1u);
        } else {
            while (*(volatile unsigned*)&g_sense == s) {}
        }
    }
    __syncthreads();
}

// ---------------- prep: tiled transpose into device scratch ----------------
__global__ void transpose_kernel(const float* __restrict__ src, int dst_sel,
                                 int rows, int cols) {
    float* dst = (dst_sel == 0) ? g_Wstk
               : (dst_sel == 1) ? (g_Wstk + NNEUR * NNEUR)
                                : g_WoutT;
    __shared__ float tile[32][33];
    int x = blockIdx.x * 32 + threadIdx.x;
    int y0 = blockIdx.y * 32;
#pragma unroll
    for (int j = 0; j < 32; j += 8) {
        int y = y0 + threadIdx.y + j;
        if (x < cols && y < rows)
            tile[threadIdx.y + j][threadIdx.x] = src[(size_t)y * cols + x];
    }
    __syncthreads();
    int xo = blockIdx.y * 32 + threadIdx.x;
    int yo0 = blockIdx.x * 32;
#pragma unroll
    for (int j = 0; j < 32; j += 8) {
        int yo = yo0 + threadIdx.y + j;
        if (xo < rows && yo < cols)
            dst[(size_t)yo * rows + xo] = tile[threadIdx.x][threadIdx.y + j];
    }
}

__global__ void zero_state_kernel() {
    int idx = blockIdx.x * blockDim.x + threadIdx.x;
    if (idx < BATCH * NNEUR) {
        g_vA[idx] = 0.0f;
        g_sA[idx] = 0.0f;
    }
}

__global__ void nop_kernel() {}

// ---------------- persistent time-loop kernel ----------------
// FROZEN numerics contract for the FEEDBACK path (bitwise-matched to ref):
//  * recurrent sum: split-K(2): k=[0,512),[512,1024), each ascending FMA
//    chain; combined P0 + P1 with one __fadd_rn. (32-k blocks keep the same
//    per-element ascending order; boundary is now at blk 16.)
//  * input projection: single ascending k=0..63 FMA chain.
//  * state update, no contraction: v' = (((0.9f*v) + accR) + accI) - s.
//  * spike: s' = (v' > 1.0f).  State reads via __ldcg (L2-coherent).
// CTAs 0..127: GEMM + state update. CTAs 128..143: action head only, executed
// AFTER the barrier, overlapped with the next step's GEMM (ping-pong parity
// guarantees head(t) readers finish before epilogue(t+2) rewrites that buffer:
// head CTAs arrive at barrier(t+1) only after head(t) completes).
__global__ __launch_bounds__(128, 1) void lif_persistent(
        const float* __restrict__ inputs, float* __restrict__ out) {
    extern __shared__ char smem_raw[];

    const int tid = threadIdx.x;
    const bool isGemm = (blockIdx.x < NGEMM);

    if (isGemm) {
        SmemG* sm = reinterpret_cast<SmemG*>(smem_raw);
        const int tx = tid & 15;            // neuron group (TN=4) -> 64 neurons
        const int ty = tid >> 4;            // row group   (TM=4) -> 32 rows
        const int bi0 = (blockIdx.x & 15) * 64;
        const int bb0 = (blockIdx.x >> 4) * 32;

        const int al_row = tid >> 2;        // A loader: row 0..31
        const int al_k   = (tid & 3) * 8;   // A loader: k offset 0,8,16,24
        const int bl_k   = tid >> 2;        // B loader: kk 0..31
        const int bl_n   = (tid & 3) * 16;  // B loader: col offset (4 float4)

        for (int t = 0; t < SEQLEN; ++t) {
            const float* __restrict__ vIn  = (t & 1) ? g_vB : g_vA;
            float* __restrict__       vOut = (t & 1) ? g_vA : g_vB;
            const float* __restrict__ sIn  = (t & 1) ? g_sB : g_sA;
            float* __restrict__       sOut = (t & 1) ? g_sA : g_sB;

            const float* aRow = &sIn[(bb0 + al_row) * NNEUR + al_k];
            const float* wRow = &g_Wstk[(size_t)bl_k * NNEUR + bi0 + bl_n];

            // ---- prologue: stage 0 (k 0..31). Safe: grid_barrier's trailing
            // __syncthreads ordered last step's readers before this store.
            {
                float4 a0 = __ldcg(reinterpret_cast<const float4*>(aRow));
                float4 a1 = __ldcg(reinterpret_cast<const float4*>(aRow + 4));
                float4 b0 = *reinterpret_cast<const float4*>(wRow);
                float4 b1 = *reinterpret_cast<const float4*>(wRow + 4);
                float4 b2 = *reinterpret_cast<const float4*>(wRow + 8);
                float4 b3 = *reinterpret_cast<const float4*>(wRow + 12);
                sm->As[0][al_k][al_row] = a0.x;     sm->As[0][al_k + 1][al_row] = a0.y;
                sm->As[0][al_k + 2][al_row] = a0.z; sm->As[0][al_k + 3][al_row] = a0.w;
                sm->As[0][al_k + 4][al_row] = a1.x; sm->As[0][al_k + 5][al_row] = a1.y;
                sm->As[0][al_k + 6][al_row] = a1.z; sm->As[0][al_k + 7][al_row] = a1.w;
                *reinterpret_cast<float4*>(&sm->Bs[0][bl_k][bl_n]) = b0;
                *reinterpret_cast<float4*>(&sm->Bs[0][bl_k][bl_n + 4]) = b1;
                *reinterpret_cast<float4*>(&sm->Bs[0][bl_k][bl_n + 8]) = b2;
                *reinterpret_cast<float4*>(&sm->Bs[0][bl_k][bl_n + 12]) = b3;
            }

            // ======== phase A1: 32 blocks of 32 k, double-buffered ========
            float accP[4][4], accQ[4][4];
#pragma unroll
            for (int m = 0; m < 4; ++m)
#pragma unroll
                for (int n = 0; n < 4; ++n) accP[m][n] = 0.0f;

            float4 a0n, a1n, b0n, b1n, b2n, b3n;
            for (int blk = 0; blk < 32; ++blk) {
                const int st = blk & 1;
                __syncthreads();                  // stage st ready
                if (blk < 31) {
                    const int kn = (blk + 1) * 32;
                    a0n = __ldcg(reinterpret_cast<const float4*>(aRow + kn));
                    a1n = __ldcg(reinterpret_cast<const float4*>(aRow + kn + 4));
                    const float* wB = wRow + (size_t)kn * NNEUR;
                    b0n = *reinterpret_cast<const float4*>(wB);
                    b1n = *reinterpret_cast<const float4*>(wB + 4);
                    b2n = *reinterpret_cast<const float4*>(wB + 8);
                    b3n = *reinterpret_cast<const float4*>(wB + 12);
                }
                if (blk == 16) {                  // split-K(2) boundary at k=512
#pragma unroll
                    for (int m = 0; m < 4; ++m)
#pragma unroll
                        for (int n = 0; n < 4; ++n) {
                            accQ[m][n] = accP[m][n];
                            accP[m][n] = 0.0f;
                        }
                }
#pragma unroll
                for (int kk = 0; kk < 32; ++kk) {
                    float4 a = *reinterpret_cast<const float4*>(&sm->As[st][kk][ty * 4]);
                    float4 b = *reinterpret_cast<const float4*>(&sm->Bs[st][kk][tx * 4]);
                    accP[0][0] = __fmaf_rn(a.x, b.x, accP[0][0]);
                    accP[0][1] = __fmaf_rn(a.x, b.y, accP[0][1]);
                    accP[0][2] = __fmaf_rn(a.x, b.z, accP[0][2]);
                    accP[0][3] = __fmaf_rn(a.x, b.w, accP[0][3]);
                    accP[1][0] = __fmaf_rn(a.y, b.x, accP[1][0]);
                    accP[1][1] = __fmaf_rn(a.y, b.y, accP[1][1]);
                    accP[1][2] = __fmaf_rn(a.y, b.z, accP[1][2]);
                    accP[1][3] = __fmaf_rn(a.y, b.w, accP[1][3]);
                    accP[2][0] = __fmaf_rn(a.z, b.x, accP[2][0]);
                    accP[2][1] = __fmaf_rn(a.z, b.y, accP[2][1]);
                    accP[2][2] = __fmaf_rn(a.z, b.z, accP[2][2]);
                    accP[2][3] = __fmaf_rn(a.z, b.w, accP[2][3]);
                    accP[3][0] = __fmaf_rn(a.w, b.x, accP[3][0]);
                    accP[3][1] = __fmaf_rn(a.w, b.y, accP[3][1]);
                    accP[3][2] = __fmaf_rn(a.w, b.z, accP[3][2]);
                    accP[3][3] = __fmaf_rn(a.w, b.w, accP[3][3]);
                }
                if (blk < 31) {
                    const int sn = st ^ 1;
                    sm->As[sn][al_k][al_row] = a0n.x;     sm->As[sn][al_k + 1][al_row] = a0n.y;
                    sm->As[sn][al_k + 2][al_row] = a0n.z; sm->As[sn][al_k + 3][al_row] = a0n.w;
                    sm->As[sn][al_k + 4][al_row] = a1n.x; sm->As[sn][al_k + 5][al_row] = a1n.y;
                    sm->As[sn][al_k + 6][al_row] = a1n.z; sm->As[sn][al_k + 7][al_row] = a1n.w;
                    *reinterpret_cast<float4*>(&sm->Bs[sn][bl_k][bl_n]) = b0n;
                    *reinterpret_cast<float4*>(&sm->Bs[sn][bl_k][bl_n + 4]) = b1n;
                    *reinterpret_cast<float4*>(&sm->Bs[sn][bl_k][bl_n + 8]) = b2n;
                    *reinterpret_cast<float4*>(&sm->Bs[sn][bl_k][bl_n + 12]) = b3n;
                }
            }
            float accS[4][4];
#pragma unroll
            for (int m = 0; m < 4; ++m)
#pragma unroll
                for (int n = 0; n < 4; ++n)
                    accS[m][n] = __fadd_rn(accQ[m][n], accP[m][n]);  // P0 + P1

            // ======== phase A2: input projection (2 blocks of 32 k) ========
            float accI[4][4];
#pragma unroll
            for (int m = 0; m < 4; ++m)
#pragma unroll
                for (int n = 0; n < 4; ++n) accI[m][n] = 0.0f;
            {
                const float* iRow = &inputs[((size_t)(bb0 + al_row) * SEQLEN + t) * OBS + al_k];
                const float* wRowI = &g_Wstk[(size_t)(NNEUR + bl_k) * NNEUR + bi0 + bl_n];
                // stage 0 safe: last read at blk30; all threads passed blk31's sync
                {
                    float4 a0 = *reinterpret_cast<const float4*>(iRow);
                    float4 a1 = *reinterpret_cast<const float4*>(iRow + 4);
                    float4 b0 = *reinterpret_cast<const float4*>(wRowI);
                    float4 b1 = *reinterpret_cast<const float4*>(wRowI + 4);
                    float4 b2 = *reinterpret_cast<const float4*>(wRowI + 8);
                    float4 b3 = *reinterpret_cast<const float4*>(wRowI + 12);
                    sm->As[0][al_k][al_row] = a0.x;     sm->As[0][al_k + 1][al_row] = a0.y;
                    sm->As[0][al_k + 2][al_row] = a0.z; sm->As[0][al_k + 3][al_row] = a0.w;
                    sm->As[0][al_k + 4][al_row] = a1.x; sm->As[0][al_k + 5][al_row] = a1.y;
                    sm->As[0][al_k + 6][al_row] = a1.z; sm->As[0][al_k + 7][al_row] = a1.w;
                    *reinterpret_cast<float4*>(&sm->Bs[0][bl_k][bl_n]) = b0;
                    *reinterpret_cast<float4*>(&sm->Bs[0][bl_k][bl_n + 4]) = b1;
                    *reinterpret_cast<float4*>(&sm->Bs[0][bl_k][bl_n + 8]) = b2;
                    *reinterpret_cast<float4*>(&sm->Bs[0][bl_k][bl_n + 12]) = b3;
                }
#pragma unroll
                for (int blk = 0; blk < 2; ++blk) {
                    const int st = blk & 1;
                    __syncthreads();
                    if (blk == 0) {
                        a0n = *reinterpret_cast<const float4*>(iRow + 32);
                        a1n = *reinterpret_cast<const float4*>(iRow + 36);
                        const float* wB = wRowI + (size_t)32 * NNEUR;
                        b0n = *reinterpret_cast<const float4*>(wB);
                        b1n = *reinterpret_cast<const float4*>(wB + 4);
                        b2n = *reinterpret_cast<const float4*>(wB + 8);
                        b3n = *reinterpret_cast<const float4*>(wB + 12);
                    }
#pragma unroll
                    for (int kk = 0; kk < 32; ++kk) {
                        float4 a = *reinterpret_cast<const float4*>(&sm->As[st][kk][ty * 4]);
                        float4 b = *reinterpret_cast<const float4*>(&sm->Bs[st][kk][tx * 4]);
                        accI[0][0] = __fmaf_rn(a.x, b.x, accI[0][0]);
                        accI[0][1] = __fmaf_rn(a.x, b.y, accI[0][1]);
                        accI[0][2] = __fmaf_rn(a.x, b.z, accI[0][2]);
                        accI[0][3] = __fmaf_rn(a.x, b.w, accI[0][3]);
                        accI[1][0] = __fmaf_rn(a.y, b.x, accI[1][0]);
                        accI[1][1] = __fmaf_rn(a.y, b.y, accI[1][1]);
                        accI[1][2] = __fmaf_rn(a.y, b.z, accI[1][2]);
                        accI[1][3] = __fmaf_rn(a.y, b.w, accI[1][3]);
                        accI[2][0] = __fmaf_rn(a.z, b.x, accI[2][0]);
                        accI[2][1] = __fmaf_rn(a.z, b.y, accI[2][1]);
                        accI[2][2] = __fmaf_rn(a.z, b.z, accI[2][2]);
                        accI[2][3] = __fmaf_rn(a.z, b.w, accI[2][3]);
                        accI[3][0] = __fmaf_rn(a.w, b.x, accI[3][0]);
                        accI[3][1] = __fmaf_rn(a.w, b.y, accI[3][1]);
                        accI[3][2] = __fmaf_rn(a.w, b.z, accI[3][2]);
                        accI[3][3] = __fmaf_rn(a.w, b.w, accI[3][3]);
                    }
                    if (blk == 0) {
                        sm->As[1][al_k][al_row] = a0n.x;     sm->As[1][al_k + 1][al_row] = a0n.y;
                        sm->As[1][al_k + 2][al_row] = a0n.z; sm->As[1][al_k + 3][al_row] = a0n.w;
                        sm->As[1][al_k + 4][al_row] = a1n.x; sm->As[1][al_k + 5][al_row] = a1n.y;
                        sm->As[1][al_k + 6][al_row] = a1n.z; sm->As[1][al_k + 7][al_row] = a1n.w;
                        *reinterpret_cast<float4*>(&sm->Bs[1][bl_k][bl_n]) = b0n;
                        *reinterpret_cast<float4*>(&sm->Bs[1][bl_k][bl_n + 4]) = b1n;
                        *reinterpret_cast<float4*>(&sm->Bs[1][bl_k][bl_n + 8]) = b2n;
                        *reinterpret_cast<float4*>(&sm->Bs[1][bl_k][bl_n + 12]) = b3n;
                    }
                }
            }

            // ---- epilogue: v' = (((0.9*v)+accS)+accI) - s — strictly NO fma ----
#pragma unroll
            for (int m = 0; m < 4; ++m) {
                int b = bb0 + ty * 4 + m;
                int idx = b * NNEUR + bi0 + tx * 4;
                float4 so4 = __ldcg(reinterpret_cast<const float4*>(&sIn[idx]));
                float4 vl4 = __ldcg(reinterpret_cast<const float4*>(&vIn[idx]));
                float v0 = __fsub_rn(__fadd_rn(__fadd_rn(__fmul_rn(BETA_C, vl4.x), accS[m][0]), accI[m][0]), so4.x);
                float v1 = __fsub_rn(__fadd_rn(__fadd_rn(__fmul_rn(BETA_C, vl4.y), accS[m][1]), accI[m][1]), so4.y);
                float v2 = __fsub_rn(__fadd_rn(__fadd_rn(__fmul_rn(BETA_C, vl4.z), accS[m][2]), accI[m][2]), so4.z);
                float v3 = __fsub_rn(__fadd_rn(__fadd_rn(__fmul_rn(BETA_C, vl4.w), accS[m][3]), accI[m][3]), so4.w);
                *reinterpret_cast<float4*>(&vOut[idx]) = make_float4(v0, v1, v2, v3);
                *reinterpret_cast<float4*>(&sOut[idx]) =
                    make_float4(v0 > VTH_C ? 1.0f : 0.0f, v1 > VTH_C ? 1.0f : 0.0f,
                                v2 > VTH_C ? 1.0f : 0.0f, v3 > VTH_C ? 1.0f : 0.0f);
            }

            grid_barrier();
            // GEMM CTAs go straight to step t+1 (opposite-parity buffers).
        }
    } else {
        // ================= head CTAs (blockIdx 128..143) =================
        SmemH* sm = reinterpret_cast<SmemH*>(smem_raw);
        const int r0 = (blockIdx.x - NGEMM) * 16;   // 16 batch rows per CTA
        const int a = tid & 63;                     // action
        const int h = tid >> 6;                     // k-half
        const int kb = h * 512;

        for (int t = 0; t < SEQLEN; ++t) {
            const float* __restrict__ vOut = (t & 1) ? g_vA : g_vB;

            grid_barrier();   // wait for step t's state (trailing __syncthreads
                              // also orders last step's v_s readers before restage)

            // stage 16 v rows (4096 float4, coalesced __ldcg)
            for (int i = tid; i < 4096; i += 128) {
                int row = i >> 8;             // 0..15
                int c4 = (i & 255) * 4;       // 0..1020
                float4 vv = __ldcg(reinterpret_cast<const float4*>(
                                &vOut[(size_t)(r0 + row) * NNEUR + c4]));
                *reinterpret_cast<float4*>(&sm->v_s[row][c4]) = vv;
            }
            __syncthreads();

            // 16 accumulators (one per row); w chunked by 4 k, reused across rows
            float acc[16];
#pragma unroll
            for (int r = 0; r < 16; ++r) acc[r] = 0.0f;
#pragma unroll 4
            for (int kc = 0; kc < 512; kc += 4) {
                float w0 = g_WoutT[(size_t)(kb + kc) * ACT + a];
                float w1 = g_WoutT[(size_t)(kb + kc + 1) * ACT + a];
                float w2 = g_WoutT[(size_t)(kb + kc + 2) * ACT + a];
                float w3 = g_WoutT[(size_t)(kb + kc + 3) * ACT + a];
#pragma unroll
                for (int r = 0; r < 16; ++r) {
                    float4 vv = *reinterpret_cast<const float4*>(&sm->v_s[r][kb + kc]);
                    acc[r] = __fmaf_rn(vv.x, w0, acc[r]);
                    acc[r] = __fmaf_rn(vv.y, w1, acc[r]);
                    acc[r] = __fmaf_rn(vv.z, w2, acc[r]);
                    acc[r] = __fmaf_rn(vv.w, w3, acc[r]);
                }
            }

            // combine k-halves via smem, h==0 threads write out
            if (h == 1) {
#pragma unroll
                for (int r = 0; r < 16; ++r) sm->red[r][a] = acc[r];
            }
            __syncthreads();
            if (h == 0) {
#pragma unroll
                for (int r = 0; r < 16; ++r) {
                    float s2 = __fadd_rn(acc[r], sm->red[r][a]);
                    out[((size_t)(r0 + r) * SEQLEN + t) * ACT + a] = tanhf(s2);
                }
            }
            // red/v_s rewritten only after the NEXT grid_barrier's syncs.
        }
    }
}

// ---------------- launch ----------------
extern "C" void kernel_launch(void* const* d_in, const int* in_sizes, int n_in,
                              void* d_out, int out_size) {
    const float* inputs = (const float*)d_in[0];   // (B, T, OBS)
    const float* W_rec  = (const float*)d_in[1];   // (N, N)
    const float* W_in   = (const float*)d_in[2];   // (N, OBS)
    const float* W_out  = (const float*)d_in[3];   // (ACT, N)
    float* out = (float*)d_out;                    // (B, T, ACT)

    cudaFuncSetAttribute(lif_persistent,
                         cudaFuncAttributeMaxDynamicSharedMemorySize, SMEM_BYTES);

    dim3 tb(32, 8);
    transpose_kernel<<<dim3(NNEUR / 32, NNEUR / 32), tb>>>(W_rec, 0, NNEUR, NNEUR);
    transpose_kernel<<<dim3(OBS / 32, NNEUR / 32), tb>>>(W_in, 1, NNEUR, OBS);
    transpose_kernel<<<dim3(NNEUR / 32, ACT / 32), tb>>>(W_out, 2, ACT, NNEUR);
    zero_state_kernel<<<(BATCH * NNEUR) / 256, 256>>>();
    nop_kernel<<<1, 32>>>();

    lif_persistent<<<NBLK, 128, SMEM_BYTES>>>(inputs, out);
}